// round 9
// baseline (speedup 1.0000x reference)
#include <cuda_runtime.h>
#include <cuda_bf16.h>

#define B_     16
#define N_     2048
#define NCTX   2047          // n_ctx = N - NQ
#define NSPLIT 64
#define OFFOUT (16LL*2048*64)

typedef unsigned long long ull;

// scratch: per-batch partial Gram matrices C (96x32) per split, and P^T (32x64)
__device__ float g_C[B_ * NSPLIT * 96 * 32];
__device__ float g_P[B_ * 32 * 64];

__device__ __forceinline__ void ffma2(ull& d, ull a, ull b) {
    asm("fma.rn.f32x2 %0, %1, %2, %0;" : "+l"(d) : "l"(a), "l"(b));
}
__device__ __forceinline__ float hsum2(ull v) {
    return __uint_as_float((unsigned)v) + __uint_as_float((unsigned)(v >> 32));
}
__device__ __forceinline__ ull dup2(float f) {
    unsigned u = __float_as_uint(f);
    return (ull)u | ((ull)u << 32);
}

// ---------------------------------------------------------------------------
// Kernel A: per (batch, split) partial C = X96[:, kv] @ Q_kv^T   (96 x 32)
// 32-n tiles (NSPLIT=64): smem 13KB, grid 1024 -> ~6.5 blocks/SM resident.
// Thread tile 6 rows x 4 q, FFMA2 over n-pairs. tile [96][34] floats
// (= stride 17 ull, odd -> row-load banks 7*rg mod 16 all distinct).
// ---------------------------------------------------------------------------
__global__ void __launch_bounds__(128) kA(const float* __restrict__ x) {
    extern __shared__ float tile[];    // 96*34 floats = 13056 B
    const int s = blockIdx.x, b = blockIdx.y;
    const int tid = threadIdx.x;
    const int rg = tid & 15;           // 16 row groups * 6 rows
    const int qg = tid >> 4;           // 8 q groups * 4 q
    const float* xb = x + (size_t)b * 160 * N_;
    const int n0 = s * 32;

    // stage 96x32 tile (zero column n >= NCTX)
#pragma unroll
    for (int i = 0; i < 6; i++) {
        const int fi = tid + i * 128;
        const int r = fi >> 3, c4 = fi & 7;
        const int n = n0 + c4 * 4;
        float4 v = *reinterpret_cast<const float4*>(&xb[r * N_ + n]);
        if (n + 4 > NCTX) {
            if (n + 0 >= NCTX) v.x = 0.f;
            if (n + 1 >= NCTX) v.y = 0.f;
            if (n + 2 >= NCTX) v.z = 0.f;
            if (n + 3 >= NCTX) v.w = 0.f;
        }
        const int base = r * 34 + c4 * 4;
        tile[base + 0] = v.x; tile[base + 1] = v.y;
        tile[base + 2] = v.z; tile[base + 3] = v.w;
    }
    __syncthreads();

    const ull* tu = reinterpret_cast<const ull*>(tile);  // row stride 17 ull

    ull acc[6][4];
#pragma unroll
    for (int k = 0; k < 6; k++)
#pragma unroll
        for (int j = 0; j < 4; j++) acc[k][j] = 0ull;

    const int rbase = rg * 6;
    const int qbase = qg * 4;
#pragma unroll 4
    for (int pp = 0; pp < 16; pp++) {
        const int nu = (pp + rg) & 15;                 // staggered n-pair slot
        ull qv[4];
#pragma unroll
        for (int j = 0; j < 4; j++) qv[j] = tu[(qbase + j) * 17 + nu];
#pragma unroll
        for (int k = 0; k < 6; k++) {
            const ull rv = tu[(rbase + k) * 17 + nu];
#pragma unroll
            for (int j = 0; j < 4; j++) ffma2(acc[k][j], rv, qv[j]);
        }
    }

    float* outp = g_C + (size_t)(b * NSPLIT + s) * 3072;
#pragma unroll
    for (int k = 0; k < 6; k++) {
        float4 o = make_float4(hsum2(acc[k][0]), hsum2(acc[k][1]),
                               hsum2(acc[k][2]), hsum2(acc[k][3]));
        *reinterpret_cast<float4*>(&outp[(rbase + k) * 32 + qbase]) = o;
    }
}

// ---------------------------------------------------------------------------
// Kernel B: per batch, reduce partial C (768 thr, 1 float4 slot each, 64
// independent LDG.128 -> MLP-saturated), then the 3-layer recursion (tid<256,
// barriers outside the guard). Tiny cost.
// ---------------------------------------------------------------------------
__global__ void __launch_bounds__(768) kB(const float* __restrict__ alpha,
                                          const float* __restrict__ kpp,
                                          const float* __restrict__ emb,
                                          const float* __restrict__ M) {
    __shared__ float sC[3072];
    __shared__ float sS[2048];
    __shared__ float sW[64 * 33];
    __shared__ float sY[2048];
    __shared__ float sWs[2048];
    const int b = blockIdx.x, tid = threadIdx.x;

    // reduce: 768 float4 slots, one per thread, 64 partials each
    {
        const float4* gc = reinterpret_cast<const float4*>(g_C + (size_t)b * (NSPLIT * 3072));
        float4 a = make_float4(0.f, 0.f, 0.f, 0.f);
#pragma unroll 8
        for (int sp = 0; sp < NSPLIT; sp++) {
            const float4 v = gc[sp * 768 + tid];
            a.x += v.x; a.y += v.y; a.z += v.z; a.w += v.w;
        }
        *reinterpret_cast<float4*>(&sC[tid * 4]) = a;
    }
    __syncthreads();

    const bool act = tid < 256;
    const int i = (tid >> 2) & 63;
    const int j0 = (tid & 3) * 8;
    float acc[8];

    if (act) {
#pragma unroll
        for (int u = 0; u < 8; u++) acc[u] = 0.f;
        for (int k = 0; k < 64; k++) {
            const float ev = emb[i * 64 + k];
            const float* row = &sC[(32 + k) * 32 + j0];
#pragma unroll
            for (int u = 0; u < 8; u++) acc[u] += ev * row[u];
        }
#pragma unroll
        for (int u = 0; u < 8; u++) { sS[i * 32 + j0 + u] = acc[u]; sWs[i * 32 + j0 + u] = 0.f; }
    }
    __syncthreads();

    const float c = kpp[0] / (float)NCTX;

    for (int l = 0; l < 3; l++) {
        if (act) {
            const float al = alpha[l * 64 + i];
#pragma unroll
            for (int u = 0; u < 8; u++) {
                const float w = al * sS[i * 32 + j0 + u];
                sW[i * 33 + j0 + u] = w;
                sWs[i * 32 + j0 + u] += w;
            }
        }
        __syncthreads();
        if (act) {
#pragma unroll
            for (int u = 0; u < 8; u++) acc[u] = 0.f;
            for (int k = 0; k < 32; k++) {
                const float wv = sW[i * 33 + k];
                const float* g = &sC[k * 32 + j0];
#pragma unroll
                for (int u = 0; u < 8; u++) acc[u] += wv * g[u];
            }
#pragma unroll
            for (int u = 0; u < 8; u++) sY[i * 32 + j0 + u] = acc[u];
        }
        __syncthreads();
        if (act) {
#pragma unroll
            for (int u = 0; u < 8; u++) acc[u] = 0.f;
            for (int k = 0; k < 64; k++) {
                const float mv = M[i * 64 + k];
                const float* y = &sY[k * 32 + j0];
#pragma unroll
                for (int u = 0; u < 8; u++) acc[u] += mv * y[u];
            }
#pragma unroll
            for (int u = 0; u < 8; u++) sS[i * 32 + j0 + u] += c * acc[u];
        }
        __syncthreads();
    }

    if (act) {
        const int cc = i;
#pragma unroll
        for (int u = 0; u < 8; u++) acc[u] = 0.f;
        for (int d = 0; d < 64; d++) {
            const float ev = emb[d * 64 + cc];
            const float* wr = &sWs[d * 32 + j0];
#pragma unroll
            for (int u = 0; u < 8; u++) acc[u] += ev * wr[u];
        }
#pragma unroll
        for (int u = 0; u < 8; u++)
            g_P[(size_t)b * 2048 + (j0 + u) * 64 + cc] = c * acc[u];
    }
}

// ---------------------------------------------------------------------------
// Kernel C: logits[b,n,:] = R^T h96[:,n] with R[k][c] = [Emb ; P^T] (96x64),
// softmax -> predictions. 32-n tiles, grid 1024, smem 36.9KB (NO padding:
// all accesses are uniform-row).
// Thread tile: c = {4cg..4cg+3} U {32+4cg..+3} (two 128B row halves -> each
// LDS.128's 8 distinct 16B addrs span exactly 128B = conflict-free) x 2 n.
// v as float2: banks 2*ng, conflict-free. Zero pack instrs in inner loop
// except 2 dup MOVs.
// ---------------------------------------------------------------------------
__global__ void __launch_bounds__(128) kC(const float* __restrict__ x,
                                          const float* __restrict__ emb,
                                          float* __restrict__ out) {
    extern __shared__ float sm[];
    float* sR = sm;                   // [96][64] floats = 24576 B
    float* sV = sm + 96 * 64;         // [96][32] floats = 12288 B
    const int pb = blockIdx.x, b = blockIdx.y;
    const int tid = threadIdx.x;
    const int cg = tid & 7;            // 8 c-groups
    const int ng = tid >> 3;           // 16 n-groups * 2 n
    const int n0 = pb * 32;
    const float* xb = x + (size_t)b * 160 * N_;

    // stage R: rows 0..63 <- Emb, rows 64..95 <- P^T  (1536 float4)
    {
        const float4* embv = reinterpret_cast<const float4*>(emb);
        const float4* gpv  = reinterpret_cast<const float4*>(g_P + (size_t)b * 2048);
        float4* sR4 = reinterpret_cast<float4*>(sR);
#pragma unroll
        for (int i = 0; i < 12; i++) {
            const int fi = tid + i * 128;
            sR4[fi] = (fi < 1024) ? embv[fi] : gpv[fi - 1024];
        }
    }
    // stage v: rows 0..63 <- x rows 96..159 (F), rows 64..95 <- x rows 0..31 (Q)
#pragma unroll
    for (int i = 0; i < 6; i++) {
        const int fi = tid + i * 128;
        const int r = fi >> 3, c4 = fi & 7;
        const int xr = (r < 64) ? (96 + r) : (r - 64);
        const float4 v = *reinterpret_cast<const float4*>(&xb[xr * N_ + n0 + c4 * 4]);
        *reinterpret_cast<float4*>(&sV[r * 32 + c4 * 4]) = v;
    }
    __syncthreads();

    ull acc[4][2];                     // [c-pair][n] ; jp 0,1 -> c 4cg+, jp 2,3 -> c 32+4cg+
#pragma unroll
    for (int jp = 0; jp < 4; jp++)
#pragma unroll
        for (int ns = 0; ns < 2; ns++) acc[jp][ns] = 0ull;

    const ulonglong2* sR2 = reinterpret_cast<const ulonglong2*>(sR);  // row stride 16
    const float2*     sV2 = reinterpret_cast<const float2*>(sV);      // row stride 16

#pragma unroll 4
    for (int t = 0; t < 96; t++) {
        const ulonglong2 rlo = sR2[t * 16 + cg];       // c = 4cg .. 4cg+3
        const ulonglong2 rhi = sR2[t * 16 + 8 + cg];   // c = 32+4cg .. +3
        const float2 vv = sV2[t * 16 + ng];            // n = 2ng, 2ng+1
        const ull dv0 = dup2(vv.x);
        const ull dv1 = dup2(vv.y);
        ull rp[4] = { rlo.x, rlo.y, rhi.x, rhi.y };
#pragma unroll
        for (int jp = 0; jp < 4; jp++) {
            ffma2(acc[jp][0], rp[jp], dv0);
            ffma2(acc[jp][1], rp[jp], dv1);
        }
    }

    // softmax over 64 c per n (8 local + reduce across 8 cg lanes) + stores
#pragma unroll
    for (int ns = 0; ns < 2; ns++) {
        float vals[8];   // vals[0..3]: c=4cg..+3 ; vals[4..7]: c=32+4cg..+3
#pragma unroll
        for (int jp = 0; jp < 4; jp++) {
            vals[2 * jp]     = __uint_as_float((unsigned)acc[jp][ns]);
            vals[2 * jp + 1] = __uint_as_float((unsigned)(acc[jp][ns] >> 32));
        }
        float m = vals[0];
#pragma unroll
        for (int u = 1; u < 8; u++) m = fmaxf(m, vals[u]);
#pragma unroll
        for (int o = 1; o < 8; o <<= 1) m = fmaxf(m, __shfl_xor_sync(0xffffffffu, m, o));
        float e[8]; float su = 0.f;
#pragma unroll
        for (int u = 0; u < 8; u++) { e[u] = __expf(vals[u] - m); su += e[u]; }
#pragma unroll
        for (int o = 1; o < 8; o <<= 1) su += __shfl_xor_sync(0xffffffffu, su, o);
        const float inv = 1.f / su;

        const int n = n0 + ng * 2 + ns;
        const size_t base = ((size_t)b * N_ + n) * 64;
        *reinterpret_cast<float4*>(&out[base + cg * 4]) =
            make_float4(vals[0], vals[1], vals[2], vals[3]);
        *reinterpret_cast<float4*>(&out[base + 32 + cg * 4]) =
            make_float4(vals[4], vals[5], vals[6], vals[7]);
        *reinterpret_cast<float4*>(&out[OFFOUT + base + cg * 4]) =
            make_float4(e[0] * inv, e[1] * inv, e[2] * inv, e[3] * inv);
        *reinterpret_cast<float4*>(&out[OFFOUT + base + 32 + cg * 4]) =
            make_float4(e[4] * inv, e[5] * inv, e[6] * inv, e[7] * inv);
    }
}

extern "C" void kernel_launch(void* const* d_in, const int* in_sizes, int n_in,
                              void* d_out, int out_size) {
    const float* x     = (const float*)d_in[0];
    const float* alpha = (const float*)d_in[1];
    const float* kp    = (const float*)d_in[2];
    const float* emb   = (const float*)d_in[3];
    const float* M     = (const float*)d_in[4];
    float* out = (float*)d_out;

    const int kaSmem = 96 * 34 * 4;               // 13056
    const int kcSmem = (96 * 64 + 96 * 32) * 4;   // 36864
    cudaFuncSetAttribute(kA, cudaFuncAttributeMaxDynamicSharedMemorySize, kaSmem);
    cudaFuncSetAttribute(kC, cudaFuncAttributeMaxDynamicSharedMemorySize, kcSmem);

    kA<<<dim3(NSPLIT, B_), 128, kaSmem>>>(x);
    kB<<<B_, 768>>>(alpha, kp, emb, M);
    kC<<<dim3(N_ / 32, B_), 128, kcSmem>>>(x, emb, out);
}

// round 10
// speedup vs baseline: 1.0217x; 1.0217x over previous
#include <cuda_runtime.h>
#include <cuda_bf16.h>

#define B_     16
#define N_     2048
#define NCTX   2047          // n_ctx = N - NQ
#define NSPLIT 32
#define OFFOUT (16LL*2048*64)

typedef unsigned long long ull;

// scratch: per-batch partial Gram matrices C (96x32) per split, reduced C, P^T
__device__ float g_C[B_ * NSPLIT * 96 * 32];
__device__ float g_Cr[B_ * 96 * 32];
__device__ float g_P[B_ * 32 * 64];

__device__ __forceinline__ void ffma2(ull& d, ull a, ull b) {
    asm("fma.rn.f32x2 %0, %1, %2, %0;" : "+l"(d) : "l"(a), "l"(b));
}
__device__ __forceinline__ float hsum2(ull v) {
    return __uint_as_float((unsigned)v) + __uint_as_float((unsigned)(v >> 32));
}
__device__ __forceinline__ ull dup2(float f) {
    unsigned u = __float_as_uint(f);
    return (ull)u | ((ull)u << 32);
}

// ---------------------------------------------------------------------------
// Kernel A: per (batch, split) partial C = X96[:, kv] @ Q_kv^T   (96 x 32)
// (R5 config: 64-n tiles, NSPLIT=32 -> smem 25.3KB, grid 512.)
// Thread tile 6 rows x 4 q, FFMA2 over n-pairs, stride-33-ull rows.
// ---------------------------------------------------------------------------
__global__ void __launch_bounds__(128) kA(const float* __restrict__ x) {
    extern __shared__ float tile[];    // 96*66 floats = 25344 B
    const int s = blockIdx.x, b = blockIdx.y;
    const int tid = threadIdx.x;
    const int rg = tid & 15;           // 16 row groups * 6 rows
    const int qg = tid >> 4;           // 8 q groups * 4 q
    const float* xb = x + (size_t)b * 160 * N_;
    const int n0 = s * 64;

    // stage 96x64 tile (zero column n >= NCTX)
#pragma unroll
    for (int i = 0; i < 12; i++) {
        const int fi = tid + i * 128;
        const int r = fi >> 4, c4 = fi & 15;
        const int n = n0 + c4 * 4;
        float4 v = *reinterpret_cast<const float4*>(&xb[r * N_ + n]);
        if (n + 4 > NCTX) {
            if (n + 0 >= NCTX) v.x = 0.f;
            if (n + 1 >= NCTX) v.y = 0.f;
            if (n + 2 >= NCTX) v.z = 0.f;
            if (n + 3 >= NCTX) v.w = 0.f;
        }
        const int base = r * 66 + c4 * 4;
        tile[base + 0] = v.x; tile[base + 1] = v.y;
        tile[base + 2] = v.z; tile[base + 3] = v.w;
    }
    __syncthreads();

    const ull* tu = reinterpret_cast<const ull*>(tile);  // row stride 33 ull

    ull acc[6][4];
#pragma unroll
    for (int k = 0; k < 6; k++)
#pragma unroll
        for (int j = 0; j < 4; j++) acc[k][j] = 0ull;

    const int rbase = rg * 6;
    const int qbase = qg * 4;
#pragma unroll 4
    for (int pp = 0; pp < 32; pp++) {
        const int nu = (pp + rg) & 31;                 // staggered n-pair slot
        ull qv[4];
#pragma unroll
        for (int j = 0; j < 4; j++) qv[j] = tu[(qbase + j) * 33 + nu];
#pragma unroll
        for (int k = 0; k < 6; k++) {
            const ull rv = tu[(rbase + k) * 33 + nu];
#pragma unroll
            for (int j = 0; j < 4; j++) ffma2(acc[k][j], rv, qv[j]);
        }
    }

    float* outp = g_C + (size_t)(b * NSPLIT + s) * 3072;
#pragma unroll
    for (int k = 0; k < 6; k++) {
        float4 o = make_float4(hsum2(acc[k][0]), hsum2(acc[k][1]),
                               hsum2(acc[k][2]), hsum2(acc[k][3]));
        *reinterpret_cast<float4*>(&outp[(rbase + k) * 32 + qbase]) = o;
    }
}

// ---------------------------------------------------------------------------
// Kernel R: wide-grid reduction of the 32 partial C's -> g_Cr[b][3072].
// grid (6, 16) x 128 thr: one float4 slot per thread, 32 independent strided
// LDG.128 (MLP-saturated), spread across ~96 SMs instead of 16.
// ---------------------------------------------------------------------------
__global__ void __launch_bounds__(128) kR() {
    const int b = blockIdx.y;
    const int slot = blockIdx.x * 128 + threadIdx.x;    // 0..767
    const float4* gc = reinterpret_cast<const float4*>(g_C + (size_t)b * (NSPLIT * 3072));
    float4 a = make_float4(0.f, 0.f, 0.f, 0.f);
#pragma unroll 8
    for (int sp = 0; sp < NSPLIT; sp++) {
        const float4 v = gc[sp * 768 + slot];
        a.x += v.x; a.y += v.y; a.z += v.z; a.w += v.w;
    }
    reinterpret_cast<float4*>(g_Cr + (size_t)b * 3072)[slot] = a;
}

// ---------------------------------------------------------------------------
// Kernel B: per batch, the closed-form 3-layer recursion on reduced C.
// grid 16 x 256 thr. Tiny.
// ---------------------------------------------------------------------------
__global__ void __launch_bounds__(256) kB(const float* __restrict__ alpha,
                                          const float* __restrict__ kpp,
                                          const float* __restrict__ emb,
                                          const float* __restrict__ M) {
    __shared__ float sC[3072];
    __shared__ float sS[2048];
    __shared__ float sW[64 * 33];
    __shared__ float sY[2048];
    __shared__ float sWs[2048];
    const int b = blockIdx.x, tid = threadIdx.x;

    {
        const float4* gcr = reinterpret_cast<const float4*>(g_Cr + (size_t)b * 3072);
        float4* sc4 = reinterpret_cast<float4*>(sC);
#pragma unroll
        for (int i = 0; i < 3; i++) sc4[tid + i * 256] = gcr[tid + i * 256];
    }
    __syncthreads();

    const int i = tid >> 2;
    const int j0 = (tid & 3) * 8;
    float acc[8];

#pragma unroll
    for (int u = 0; u < 8; u++) acc[u] = 0.f;
    for (int k = 0; k < 64; k++) {
        const float ev = emb[i * 64 + k];
        const float* row = &sC[(32 + k) * 32 + j0];
#pragma unroll
        for (int u = 0; u < 8; u++) acc[u] += ev * row[u];
    }
#pragma unroll
    for (int u = 0; u < 8; u++) { sS[i * 32 + j0 + u] = acc[u]; sWs[i * 32 + j0 + u] = 0.f; }
    __syncthreads();

    const float c = kpp[0] / (float)NCTX;

    for (int l = 0; l < 3; l++) {
        const float al = alpha[l * 64 + i];
#pragma unroll
        for (int u = 0; u < 8; u++) {
            const float w = al * sS[i * 32 + j0 + u];
            sW[i * 33 + j0 + u] = w;
            sWs[i * 32 + j0 + u] += w;
        }
        __syncthreads();
#pragma unroll
        for (int u = 0; u < 8; u++) acc[u] = 0.f;
        for (int k = 0; k < 32; k++) {
            const float wv = sW[i * 33 + k];
            const float* g = &sC[k * 32 + j0];
#pragma unroll
            for (int u = 0; u < 8; u++) acc[u] += wv * g[u];
        }
#pragma unroll
        for (int u = 0; u < 8; u++) sY[i * 32 + j0 + u] = acc[u];
        __syncthreads();
#pragma unroll
        for (int u = 0; u < 8; u++) acc[u] = 0.f;
        for (int k = 0; k < 64; k++) {
            const float mv = M[i * 64 + k];
            const float* y = &sY[k * 32 + j0];
#pragma unroll
            for (int u = 0; u < 8; u++) acc[u] += mv * y[u];
        }
#pragma unroll
        for (int u = 0; u < 8; u++) sS[i * 32 + j0 + u] += c * acc[u];
        __syncthreads();
    }

    const int cc = i;
#pragma unroll
    for (int u = 0; u < 8; u++) acc[u] = 0.f;
    for (int d = 0; d < 64; d++) {
        const float ev = emb[d * 64 + cc];
        const float* wr = &sWs[d * 32 + j0];
#pragma unroll
        for (int u = 0; u < 8; u++) acc[u] += ev * wr[u];
    }
#pragma unroll
    for (int u = 0; u < 8; u++)
        g_P[(size_t)b * 2048 + (j0 + u) * 64 + cc] = c * acc[u];
}

// ---------------------------------------------------------------------------
// Kernel C: logits[b,n,:] = R^T h96[:,n], R = [Emb ; P^T] (96x64); softmax.
// 64-n tiles, grid 512, smem 48KB -> 4 blocks/SM, single fully-resident wave.
// Thread tile 8c x 4n (16 ull accs). Per k-iter: 2 R LDS.128 (1 wf each,
// natural c-pairs) + 1 v LDS.128 (4 distinct 16B -> 1 wf) + 4 dup MOV-pairs
// (ALU pipe, co-issues) + 16 FFMA2. Softmax across the 8 cg lanes (xor 1,2,4).
// ---------------------------------------------------------------------------
__global__ void __launch_bounds__(128) kC(const float* __restrict__ x,
                                          const float* __restrict__ emb,
                                          float* __restrict__ out) {
    extern __shared__ float sm[];
    float* sR = sm;                   // [96][64] floats = 24576 B
    float* sV = sm + 96 * 64;         // [96][64] floats = 24576 B
    const int pb = blockIdx.x, b = blockIdx.y;
    const int tid = threadIdx.x;
    const int cg = tid & 7;            // 8 c-groups * 8 c
    const int ng = tid >> 3;           // 16 n-groups * 4 n
    const int n0 = pb * 64;
    const float* xb = x + (size_t)b * 160 * N_;

    // stage R: rows 0..63 <- Emb, rows 64..95 <- P^T  (1536 float4)
    {
        const float4* embv = reinterpret_cast<const float4*>(emb);
        const float4* gpv  = reinterpret_cast<const float4*>(g_P + (size_t)b * 2048);
        float4* sR4 = reinterpret_cast<float4*>(sR);
#pragma unroll
        for (int i = 0; i < 12; i++) {
            const int fi = tid + i * 128;
            sR4[fi] = (fi < 1024) ? embv[fi] : gpv[fi - 1024];
        }
    }
    // stage v: rows 0..63 <- x rows 96..159 (F), rows 64..95 <- x rows 0..31 (Q)
#pragma unroll
    for (int i = 0; i < 12; i++) {
        const int fi = tid + i * 128;
        const int r = fi >> 4, c4 = fi & 15;
        const int xr = (r < 64) ? (96 + r) : (r - 64);
        const float4 v = *reinterpret_cast<const float4*>(&xb[xr * N_ + n0 + c4 * 4]);
        *reinterpret_cast<float4*>(&sV[r * 64 + c4 * 4]) = v;
    }
    __syncthreads();

    ull acc[4][4];                     // [c-pair jp][n ns]; c = 8cg+2jp(+1)
#pragma unroll
    for (int jp = 0; jp < 4; jp++)
#pragma unroll
        for (int ns = 0; ns < 4; ns++) acc[jp][ns] = 0ull;

    const ulonglong2* sR2 = reinterpret_cast<const ulonglong2*>(sR);  // row = 16 units
    const float4*     sV4 = reinterpret_cast<const float4*>(sV);      // row = 16 units

#pragma unroll 4
    for (int t = 0; t < 96; t++) {
        const ulonglong2 rlo = sR2[t * 16 + cg * 2];       // c = 8cg .. +3
        const ulonglong2 rhi = sR2[t * 16 + cg * 2 + 1];   // c = 8cg+4 .. +7
        const float4 vv = sV4[t * 16 + ng];                // n = 4ng .. +3
        ull dv[4];
        dv[0] = dup2(vv.x); dv[1] = dup2(vv.y);
        dv[2] = dup2(vv.z); dv[3] = dup2(vv.w);
        ull rp[4] = { rlo.x, rlo.y, rhi.x, rhi.y };
#pragma unroll
        for (int jp = 0; jp < 4; jp++)
#pragma unroll
            for (int ns = 0; ns < 4; ns++) ffma2(acc[jp][ns], rp[jp], dv[ns]);
    }

    // softmax over 64 c per n (8 local + reduce across 8 cg lanes) + stores
#pragma unroll
    for (int ns = 0; ns < 4; ns++) {
        float vals[8];   // c = 8cg + u
#pragma unroll
        for (int jp = 0; jp < 4; jp++) {
            vals[2 * jp]     = __uint_as_float((unsigned)acc[jp][ns]);
            vals[2 * jp + 1] = __uint_as_float((unsigned)(acc[jp][ns] >> 32));
        }
        float m = vals[0];
#pragma unroll
        for (int u = 1; u < 8; u++) m = fmaxf(m, vals[u]);
#pragma unroll
        for (int o = 1; o < 8; o <<= 1) m = fmaxf(m, __shfl_xor_sync(0xffffffffu, m, o));
        float e[8]; float su = 0.f;
#pragma unroll
        for (int u = 0; u < 8; u++) { e[u] = __expf(vals[u] - m); su += e[u]; }
#pragma unroll
        for (int o = 1; o < 8; o <<= 1) su += __shfl_xor_sync(0xffffffffu, su, o);
        const float inv = 1.f / su;

        const int n = n0 + ng * 4 + ns;
        const size_t base = ((size_t)b * N_ + n) * 64 + cg * 8;
        *reinterpret_cast<float4*>(&out[base])     = make_float4(vals[0], vals[1], vals[2], vals[3]);
        *reinterpret_cast<float4*>(&out[base + 4]) = make_float4(vals[4], vals[5], vals[6], vals[7]);
        *reinterpret_cast<float4*>(&out[OFFOUT + base]) =
            make_float4(e[0] * inv, e[1] * inv, e[2] * inv, e[3] * inv);
        *reinterpret_cast<float4*>(&out[OFFOUT + base + 4]) =
            make_float4(e[4] * inv, e[5] * inv, e[6] * inv, e[7] * inv);
    }
}

extern "C" void kernel_launch(void* const* d_in, const int* in_sizes, int n_in,
                              void* d_out, int out_size) {
    const float* x     = (const float*)d_in[0];
    const float* alpha = (const float*)d_in[1];
    const float* kp    = (const float*)d_in[2];
    const float* emb   = (const float*)d_in[3];
    const float* M     = (const float*)d_in[4];
    float* out = (float*)d_out;

    const int kaSmem = 96 * 66 * 4;       // 25344
    const int kcSmem = 2 * 96 * 64 * 4;   // 49152
    cudaFuncSetAttribute(kA, cudaFuncAttributeMaxDynamicSharedMemorySize, kaSmem);
    cudaFuncSetAttribute(kC, cudaFuncAttributeMaxDynamicSharedMemorySize, kcSmem);

    kA<<<dim3(NSPLIT, B_), 128, kaSmem>>>(x);
    kR<<<dim3(6, B_), 128>>>();
    kB<<<B_, 256>>>(alpha, kp, emb, M);
    kC<<<dim3(N_ / 64, B_), 128, kcSmem>>>(x, emb, out);
}

// round 11
// speedup vs baseline: 1.1992x; 1.1738x over previous
#include <cuda_runtime.h>
#include <cuda_bf16.h>

#define B_     16
#define N_     2048
#define NCTX   2047          // n_ctx = N - NQ
#define NSPLIT 32
#define OFFOUT (16LL*2048*64)

typedef unsigned long long ull;

// scratch: per-batch partial Gram matrices C (96x32) per split, and P^T (32x64)
__device__ float g_C[B_ * NSPLIT * 96 * 32];
__device__ float g_P[B_ * 32 * 64];

__device__ __forceinline__ void ffma2(ull& d, ull a, ull b) {
    asm("fma.rn.f32x2 %0, %1, %2, %0;" : "+l"(d) : "l"(a), "l"(b));
}
__device__ __forceinline__ float hsum2(ull v) {
    return __uint_as_float((unsigned)v) + __uint_as_float((unsigned)(v >> 32));
}
__device__ __forceinline__ ull dup2(float f) {
    unsigned u = __float_as_uint(f);
    return (ull)u | ((ull)u << 32);
}

// ---------------------------------------------------------------------------
// Kernel A: per (batch, split) partial C = X96[:, kv] @ Q_kv^T   (96 x 32)
// 64-n tiles, NSPLIT=32, smem 25.3KB, grid 512. Thread tile 6r x 4q, FFMA2
// over n-pairs, stride-33-ull rows (conflict-free via rg stagger).
// NEW: explicit 2-deep register prefetch pipeline + reg cap 128 (lb 128,4)
// so the 10 LDS/iter are issued one iteration ahead of their use.
// ---------------------------------------------------------------------------
__global__ void __launch_bounds__(128, 4) kA(const float* __restrict__ x) {
    extern __shared__ float tile[];    // 96*66 floats = 25344 B
    const int s = blockIdx.x, b = blockIdx.y;
    const int tid = threadIdx.x;
    const int rg = tid & 15;           // 16 row groups * 6 rows
    const int qg = tid >> 4;           // 8 q groups * 4 q
    const float* xb = x + (size_t)b * 160 * N_;
    const int n0 = s * 64;

    // stage 96x64 tile (zero column n >= NCTX)
#pragma unroll
    for (int i = 0; i < 12; i++) {
        const int fi = tid + i * 128;
        const int r = fi >> 4, c4 = fi & 15;
        const int n = n0 + c4 * 4;
        float4 v = *reinterpret_cast<const float4*>(&xb[r * N_ + n]);
        if (n + 4 > NCTX) {
            if (n + 0 >= NCTX) v.x = 0.f;
            if (n + 1 >= NCTX) v.y = 0.f;
            if (n + 2 >= NCTX) v.z = 0.f;
            if (n + 3 >= NCTX) v.w = 0.f;
        }
        const int base = r * 66 + c4 * 4;
        tile[base + 0] = v.x; tile[base + 1] = v.y;
        tile[base + 2] = v.z; tile[base + 3] = v.w;
    }
    __syncthreads();

    const ull* tu = reinterpret_cast<const ull*>(tile);  // row stride 33 ull

    ull acc[6][4];
#pragma unroll
    for (int k = 0; k < 6; k++)
#pragma unroll
        for (int j = 0; j < 4; j++) acc[k][j] = 0ull;

    const int rbase = rg * 6;
    const int qbase = qg * 4;

    ull qv[2][4], rv[2][6];
    {
        const int nu = rg & 31;        // pp = 0 slot
#pragma unroll
        for (int j = 0; j < 4; j++) qv[0][j] = tu[(qbase + j) * 33 + nu];
#pragma unroll
        for (int k = 0; k < 6; k++) rv[0][k] = tu[(rbase + k) * 33 + nu];
    }

#pragma unroll 2
    for (int pp = 0; pp < 32; pp++) {
        const int cur = pp & 1, nxt = cur ^ 1;
        if (pp < 31) {
            const int nu = (pp + 1 + rg) & 31;
#pragma unroll
            for (int j = 0; j < 4; j++) qv[nxt][j] = tu[(qbase + j) * 33 + nu];
#pragma unroll
            for (int k = 0; k < 6; k++) rv[nxt][k] = tu[(rbase + k) * 33 + nu];
        }
#pragma unroll
        for (int k = 0; k < 6; k++)
#pragma unroll
            for (int j = 0; j < 4; j++) ffma2(acc[k][j], rv[cur][k], qv[cur][j]);
    }

    float* outp = g_C + (size_t)(b * NSPLIT + s) * 3072;
#pragma unroll
    for (int k = 0; k < 6; k++) {
        float4 o = make_float4(hsum2(acc[k][0]), hsum2(acc[k][1]),
                               hsum2(acc[k][2]), hsum2(acc[k][3]));
        *reinterpret_cast<float4*>(&outp[(rbase + k) * 32 + qbase]) = o;
    }
}

// ---------------------------------------------------------------------------
// Kernel B (fused reduce + recursion): 768 thr. Reduce: one float4 slot per
// thread, 32 independent strided LDG.128 (MLP-saturated). Recursion on
// tid<256 with barriers hoisted out of the guard.
// ---------------------------------------------------------------------------
__global__ void __launch_bounds__(768) kB(const float* __restrict__ alpha,
                                          const float* __restrict__ kpp,
                                          const float* __restrict__ emb,
                                          const float* __restrict__ M) {
    __shared__ float sC[3072];
    __shared__ float sS[2048];
    __shared__ float sW[64 * 33];
    __shared__ float sY[2048];
    __shared__ float sWs[2048];
    const int b = blockIdx.x, tid = threadIdx.x;

    {
        const float4* gc = reinterpret_cast<const float4*>(g_C + (size_t)b * (NSPLIT * 3072));
        float4 a = make_float4(0.f, 0.f, 0.f, 0.f);
#pragma unroll 8
        for (int sp = 0; sp < NSPLIT; sp++) {
            const float4 v = gc[sp * 768 + tid];
            a.x += v.x; a.y += v.y; a.z += v.z; a.w += v.w;
        }
        *reinterpret_cast<float4*>(&sC[tid * 4]) = a;
    }
    __syncthreads();

    const bool act = tid < 256;
    const int i = (tid >> 2) & 63;
    const int j0 = (tid & 3) * 8;
    float acc[8];

    if (act) {
#pragma unroll
        for (int u = 0; u < 8; u++) acc[u] = 0.f;
        for (int k = 0; k < 64; k++) {
            const float ev = emb[i * 64 + k];
            const float* row = &sC[(32 + k) * 32 + j0];
#pragma unroll
            for (int u = 0; u < 8; u++) acc[u] += ev * row[u];
        }
#pragma unroll
        for (int u = 0; u < 8; u++) { sS[i * 32 + j0 + u] = acc[u]; sWs[i * 32 + j0 + u] = 0.f; }
    }
    __syncthreads();

    const float c = kpp[0] / (float)NCTX;

    for (int l = 0; l < 3; l++) {
        if (act) {
            const float al = alpha[l * 64 + i];
#pragma unroll
            for (int u = 0; u < 8; u++) {
                const float w = al * sS[i * 32 + j0 + u];
                sW[i * 33 + j0 + u] = w;
                sWs[i * 32 + j0 + u] += w;
            }
        }
        __syncthreads();
        if (act) {
#pragma unroll
            for (int u = 0; u < 8; u++) acc[u] = 0.f;
            for (int k = 0; k < 32; k++) {
                const float wv = sW[i * 33 + k];
                const float* g = &sC[k * 32 + j0];
#pragma unroll
                for (int u = 0; u < 8; u++) acc[u] += wv * g[u];
            }
#pragma unroll
            for (int u = 0; u < 8; u++) sY[i * 32 + j0 + u] = acc[u];
        }
        __syncthreads();
        if (act) {
#pragma unroll
            for (int u = 0; u < 8; u++) acc[u] = 0.f;
            for (int k = 0; k < 64; k++) {
                const float mv = M[i * 64 + k];
                const float* y = &sY[k * 32 + j0];
#pragma unroll
                for (int u = 0; u < 8; u++) acc[u] += mv * y[u];
            }
#pragma unroll
            for (int u = 0; u < 8; u++) sS[i * 32 + j0 + u] += c * acc[u];
        }
        __syncthreads();
    }

    if (act) {
        const int cc = i;
#pragma unroll
        for (int u = 0; u < 8; u++) acc[u] = 0.f;
        for (int d = 0; d < 64; d++) {
            const float ev = emb[d * 64 + cc];
            const float* wr = &sWs[d * 32 + j0];
#pragma unroll
            for (int u = 0; u < 8; u++) acc[u] += ev * wr[u];
        }
#pragma unroll
        for (int u = 0; u < 8; u++)
            g_P[(size_t)b * 2048 + (j0 + u) * 64 + cc] = c * acc[u];
    }
}

// ---------------------------------------------------------------------------
// Kernel C: logits[b,n,:] = R^T h96[:,n], R = [Emb ; P^T] (96x64); softmax.
// 64-n tiles, grid 512, smem 48KB -> 4 blocks/SM resident, reg cap 128.
// CONFLICT-FREE c-mapping: thread c = {4cg..+3} U {32+4cg..+3} -> each
// LDS.128's 8 distinct 16B addrs span exactly 128B (R9 mapping; the R10
// cg*2 mapping was 2-way conflicted). v: uniform-row broadcast per phase.
// 2-deep register prefetch pipeline hides the 29-cyc LDS latency.
// ---------------------------------------------------------------------------
__global__ void __launch_bounds__(128, 4) kC(const float* __restrict__ x,
                                             const float* __restrict__ emb,
                                             float* __restrict__ out) {
    extern __shared__ float sm[];
    float* sR = sm;                   // [96][64] floats = 24576 B
    float* sV = sm + 96 * 64;         // [96][64] floats = 24576 B
    const int pb = blockIdx.x, b = blockIdx.y;
    const int tid = threadIdx.x;
    const int cg = tid & 7;            // 8 c-groups
    const int ng = tid >> 3;           // 16 n-groups * 4 n
    const int n0 = pb * 64;
    const float* xb = x + (size_t)b * 160 * N_;

    // stage R: rows 0..63 <- Emb, rows 64..95 <- P^T  (1536 float4)
    {
        const float4* embv = reinterpret_cast<const float4*>(emb);
        const float4* gpv  = reinterpret_cast<const float4*>(g_P + (size_t)b * 2048);
        float4* sR4 = reinterpret_cast<float4*>(sR);
#pragma unroll
        for (int i = 0; i < 12; i++) {
            const int fi = tid + i * 128;
            sR4[fi] = (fi < 1024) ? embv[fi] : gpv[fi - 1024];
        }
    }
    // stage v: rows 0..63 <- x rows 96..159 (F), rows 64..95 <- x rows 0..31 (Q)
#pragma unroll
    for (int i = 0; i < 12; i++) {
        const int fi = tid + i * 128;
        const int r = fi >> 4, c4 = fi & 15;
        const int xr = (r < 64) ? (96 + r) : (r - 64);
        const float4 v = *reinterpret_cast<const float4*>(&xb[xr * N_ + n0 + c4 * 4]);
        *reinterpret_cast<float4*>(&sV[r * 64 + c4 * 4]) = v;
    }
    __syncthreads();

    ull acc[4][4];       // jp 0,1 -> c = 4cg..+3 ; jp 2,3 -> c = 32+4cg..+3
#pragma unroll
    for (int jp = 0; jp < 4; jp++)
#pragma unroll
        for (int ns = 0; ns < 4; ns++) acc[jp][ns] = 0ull;

    const ulonglong2* sR2 = reinterpret_cast<const ulonglong2*>(sR);  // row = 16 units
    const float4*     sV4 = reinterpret_cast<const float4*>(sV);      // row = 16 units

    ulonglong2 rlo[2], rhi[2];
    float4 vv[2];
    rlo[0] = sR2[cg];          // t = 0
    rhi[0] = sR2[8 + cg];
    vv[0]  = sV4[ng];

#pragma unroll 2
    for (int t = 0; t < 96; t++) {
        const int cur = t & 1, nxt = cur ^ 1;
        if (t < 95) {
            rlo[nxt] = sR2[(t + 1) * 16 + cg];
            rhi[nxt] = sR2[(t + 1) * 16 + 8 + cg];
            vv[nxt]  = sV4[(t + 1) * 16 + ng];
        }
        ull dv[4];
        dv[0] = dup2(vv[cur].x); dv[1] = dup2(vv[cur].y);
        dv[2] = dup2(vv[cur].z); dv[3] = dup2(vv[cur].w);
        const ull rp[4] = { rlo[cur].x, rlo[cur].y, rhi[cur].x, rhi[cur].y };
#pragma unroll
        for (int jp = 0; jp < 4; jp++)
#pragma unroll
            for (int ns = 0; ns < 4; ns++) ffma2(acc[jp][ns], rp[jp], dv[ns]);
    }

    // softmax over 64 c per n (8 local + reduce across 8 cg lanes) + stores
#pragma unroll
    for (int ns = 0; ns < 4; ns++) {
        float vals[8];   // vals[0..3]: c=4cg..+3 ; vals[4..7]: c=32+4cg..+3
#pragma unroll
        for (int jp = 0; jp < 4; jp++) {
            vals[2 * jp]     = __uint_as_float((unsigned)acc[jp][ns]);
            vals[2 * jp + 1] = __uint_as_float((unsigned)(acc[jp][ns] >> 32));
        }
        float m = vals[0];
#pragma unroll
        for (int u = 1; u < 8; u++) m = fmaxf(m, vals[u]);
#pragma unroll
        for (int o = 1; o < 8; o <<= 1) m = fmaxf(m, __shfl_xor_sync(0xffffffffu, m, o));
        float e[8]; float su = 0.f;
#pragma unroll
        for (int u = 0; u < 8; u++) { e[u] = __expf(vals[u] - m); su += e[u]; }
#pragma unroll
        for (int o = 1; o < 8; o <<= 1) su += __shfl_xor_sync(0xffffffffu, su, o);
        const float inv = 1.f / su;

        const int n = n0 + ng * 4 + ns;
        const size_t base = ((size_t)b * N_ + n) * 64;
        *reinterpret_cast<float4*>(&out[base + cg * 4]) =
            make_float4(vals[0], vals[1], vals[2], vals[3]);
        *reinterpret_cast<float4*>(&out[base + 32 + cg * 4]) =
            make_float4(vals[4], vals[5], vals[6], vals[7]);
        *reinterpret_cast<float4*>(&out[OFFOUT + base + cg * 4]) =
            make_float4(e[0] * inv, e[1] * inv, e[2] * inv, e[3] * inv);
        *reinterpret_cast<float4*>(&out[OFFOUT + base + 32 + cg * 4]) =
            make_float4(e[4] * inv, e[5] * inv, e[6] * inv, e[7] * inv);
    }
}

extern "C" void kernel_launch(void* const* d_in, const int* in_sizes, int n_in,
                              void* d_out, int out_size) {
    const float* x     = (const float*)d_in[0];
    const float* alpha = (const float*)d_in[1];
    const float* kp    = (const float*)d_in[2];
    const float* emb   = (const float*)d_in[3];
    const float* M     = (const float*)d_in[4];
    float* out = (float*)d_out;

    const int kaSmem = 96 * 66 * 4;       // 25344
    const int kcSmem = 2 * 96 * 64 * 4;   // 49152
    cudaFuncSetAttribute(kA, cudaFuncAttributeMaxDynamicSharedMemorySize, kaSmem);
    cudaFuncSetAttribute(kC, cudaFuncAttributeMaxDynamicSharedMemorySize, kcSmem);

    kA<<<dim3(NSPLIT, B_), 128, kaSmem>>>(x);
    kB<<<B_, 768>>>(alpha, kp, emb, M);
    kC<<<dim3(N_ / 64, B_), 128, kcSmem>>>(x, emb, out);
}